// round 1
// baseline (speedup 1.0000x reference)
#include <cuda_runtime.h>
#include <cuda_bf16.h>
#include <cstdint>
#include <cmath>

// ---------------- problem sizes ----------------
#define T_STEPS 256
#define BATCH   64
#define KDIM    1024    // D = H = 1024
#define NGATE   4096    // 4H

// ---------------- scratch (device globals; no allocation allowed) ----------------
__device__ float g_Z0[(size_t)T_STEPS * BATCH * NGATE];   // x-projection layer 0 (+bias)
__device__ float g_Z1[(size_t)T_STEPS * BATCH * NGATE];   // x-projection layer 1 (+bias)
__device__ float g_H1[(size_t)T_STEPS * BATCH * KDIM];    // layer-1 hidden outputs
__device__ float g_c0[BATCH * KDIM];                      // cell state layer 0
__device__ float g_c1[BATCH * KDIM];                      // cell state layer 1
__device__ float g_zero[BATCH * KDIM];                    // never written: stays zero (h_{-1})

#define DEVFN __device__ __forceinline__

// ---------------- tf32 helpers ----------------
DEVFN uint32_t cvt_tf32(float x) {
    uint32_t r;
    asm("cvt.rna.tf32.f32 %0, %1;" : "=r"(r) : "f"(x));
    return r;
}
DEVFN void split_tf32(float x, uint32_t& hi, uint32_t& lo) {
    hi = cvt_tf32(x);
    lo = cvt_tf32(x - __uint_as_float(hi));
}
DEVFN void mma8(float* c, uint32_t a0, uint32_t a1, uint32_t a2, uint32_t a3,
                uint32_t b0, uint32_t b1) {
    asm volatile(
        "mma.sync.aligned.m16n8k8.row.col.f32.tf32.tf32.f32 "
        "{%0,%1,%2,%3},{%4,%5,%6,%7},{%8,%9},{%0,%1,%2,%3};"
        : "+f"(c[0]), "+f"(c[1]), "+f"(c[2]), "+f"(c[3])
        : "r"(a0), "r"(a1), "r"(a2), "r"(a3), "r"(b0), "r"(b1));
}

// ---------------- cp.async helpers ----------------
DEVFN void cp16(void* s, const void* g) {
    uint32_t sa = (uint32_t)__cvta_generic_to_shared(s);
    asm volatile("cp.async.cg.shared.global [%0], [%1], 16;" :: "r"(sa), "l"(g));
}
DEVFN void cp_commit() { asm volatile("cp.async.commit_group;"); }
template <int N> DEVFN void cp_wait() { asm volatile("cp.async.wait_group %0;" :: "n"(N)); }

// ======================================================================
// Pre-GEMM:  C[M, 4096] = A[M, 1024] @ W[1024, 4096] + bias   (3xTF32)
// Tile 128x128x16, 256 threads (8 warps: 4(M) x 2(N)), 2-stage cp.async.
// ======================================================================
#define PBM 128
#define PBN 128
#define PBK 16
#define PNT (KDIM / PBK)   // 64

__global__ __launch_bounds__(256) void gemm_pre(
    const float* __restrict__ A, const float* __restrict__ W,
    const float* __restrict__ bias, float* __restrict__ C)
{
    __shared__ float sA[2][PBM][PBK + 4];   // [128][20], conflict-free frag loads
    __shared__ float sB[2][PBK][PBN + 8];   // [16][136]

    const int tid  = threadIdx.x;
    const int warp = tid >> 5, lane = tid & 31;
    const int g  = lane >> 2, t4 = lane & 3;
    const int wm = warp >> 1, wn = warp & 1;
    const int m0 = blockIdx.y * PBM;
    const int n0 = blockIdx.x * PBN;

    float acc[2][8][4];
    #pragma unroll
    for (int i = 0; i < 2; i++)
        #pragma unroll
        for (int j = 0; j < 8; j++)
            #pragma unroll
            for (int k = 0; k < 4; k++) acc[i][j][k] = 0.f;

    auto issue = [&](int kt, int s) {
        #pragma unroll
        for (int p = 0; p < 2; p++) {               // A: 128x16 = 512 float4
            int idx = p * 256 + tid;
            int row = idx >> 2, c4 = idx & 3;
            cp16(&sA[s][row][c4 * 4], A + (size_t)(m0 + row) * KDIM + kt * PBK + c4 * 4);
        }
        #pragma unroll
        for (int p = 0; p < 2; p++) {               // B: 16x128 = 512 float4
            int idx = p * 256 + tid;
            int row = idx >> 5, c4 = idx & 31;
            cp16(&sB[s][row][c4 * 4], W + (size_t)(kt * PBK + row) * NGATE + n0 + c4 * 4);
        }
    };

    issue(0, 0); cp_commit();

    for (int kt = 0; kt < PNT; kt++) {
        cp_wait<0>();
        __syncthreads();                             // tile kt visible to all; prev compute done
        if (kt + 1 < PNT) issue(kt + 1, (kt + 1) & 1);
        cp_commit();
        const int s = kt & 1;

        #pragma unroll
        for (int k8 = 0; k8 < PBK / 8; k8++) {
            const int k0 = k8 * 8;
            uint32_t ah[2][4], al[2][4];
            #pragma unroll
            for (int mf = 0; mf < 2; mf++) {
                int m = wm * 32 + mf * 16 + g;
                split_tf32(sA[s][m    ][k0 + t4    ], ah[mf][0], al[mf][0]);
                split_tf32(sA[s][m + 8][k0 + t4    ], ah[mf][1], al[mf][1]);
                split_tf32(sA[s][m    ][k0 + t4 + 4], ah[mf][2], al[mf][2]);
                split_tf32(sA[s][m + 8][k0 + t4 + 4], ah[mf][3], al[mf][3]);
            }
            #pragma unroll
            for (int nf = 0; nf < 8; nf++) {
                int n = wn * 64 + nf * 8 + g;
                uint32_t bh0, bl0, bh1, bl1;
                split_tf32(sB[s][k0 + t4    ][n], bh0, bl0);
                split_tf32(sB[s][k0 + t4 + 4][n], bh1, bl1);
                #pragma unroll
                for (int mf = 0; mf < 2; mf++) {
                    mma8(acc[mf][nf], ah[mf][0], ah[mf][1], ah[mf][2], ah[mf][3], bh0, bh1);
                    mma8(acc[mf][nf], al[mf][0], al[mf][1], al[mf][2], al[mf][3], bh0, bh1);
                    mma8(acc[mf][nf], ah[mf][0], ah[mf][1], ah[mf][2], ah[mf][3], bl0, bl1);
                }
            }
        }
    }

    // epilogue: +bias, store
    #pragma unroll
    for (int mf = 0; mf < 2; mf++) {
        #pragma unroll
        for (int nf = 0; nf < 8; nf++) {
            int col = n0 + wn * 64 + nf * 8 + 2 * t4;
            int r0  = m0 + wm * 32 + mf * 16 + g;
            float bv0 = bias[col], bv1 = bias[col + 1];
            C[(size_t)r0 * NGATE + col]           = acc[mf][nf][0] + bv0;
            C[(size_t)r0 * NGATE + col + 1]       = acc[mf][nf][1] + bv1;
            C[(size_t)(r0 + 8) * NGATE + col]     = acc[mf][nf][2] + bv0;
            C[(size_t)(r0 + 8) * NGATE + col + 1] = acc[mf][nf][3] + bv1;
        }
    }
}

// ======================================================================
// Fused LSTM step:  z = Zx[t] + h_prev @ Wh ; gates ; c,h update.
// Grid: 128 CTAs, each owns 8 h-columns (-> 32 z-columns: 4 gates x 8).
// 128 threads (4 warps x 16 rows). 3-stage cp.async K-pipeline. 3xTF32.
// ======================================================================
#define SBK 32
#define SNT (KDIM / SBK)   // 32

__global__ __launch_bounds__(128) void lstm_step(
    const float* __restrict__ Zx,     // [64, 4096] slice for this t (bias already added)
    const float* __restrict__ hprev,  // [64, 1024]
    float* __restrict__ cbuf,         // [64, 1024] in/out
    const float* __restrict__ Wh,     // [1024, 4096]
    float* __restrict__ hout)         // [64, 1024] slice for this t
{
    __shared__ float sA[3][BATCH][SBK + 4];   // h tile [64][36]
    __shared__ float sB[3][SBK][32 + 8];      // W tile [32][40] (4 gates x 8 cols)

    const int tid  = threadIdx.x;
    const int warp = tid >> 5, lane = tid & 31;
    const int g  = lane >> 2, t4 = lane & 3;
    const int n0 = blockIdx.x * 8;            // h-column base

    float acc[4][4] = {};                     // acc[gate][creg]

    auto issue = [&](int kt, int s) {
        #pragma unroll
        for (int p = 0; p < 4; p++) {         // h: 64x32 = 512 float4
            int idx = p * 128 + tid;
            int row = idx >> 3, c4 = idx & 7;
            cp16(&sA[s][row][c4 * 4], hprev + (size_t)row * KDIM + kt * SBK + c4 * 4);
        }
        #pragma unroll
        for (int p = 0; p < 2; p++) {         // W: 32 rows x (4 gates x 8 cols) = 256 float4
            int idx = p * 128 + tid;
            int row = idx >> 3, q = idx & 7;  // q: gate = q>>1, half = q&1
            cp16(&sB[s][row][q * 4],
                 Wh + (size_t)(kt * SBK + row) * NGATE + (q >> 1) * 1024 + n0 + (q & 1) * 4);
        }
    };

    issue(0, 0); cp_commit();
    issue(1, 1); cp_commit();

    for (int kt = 0; kt < SNT; kt++) {
        cp_wait<1>();                         // stage kt complete (always 2 groups pending)
        __syncthreads();
        if (kt + 2 < SNT) issue(kt + 2, (kt + 2) % 3);
        cp_commit();                          // commit every iter (possibly empty) to keep count
        const int s = kt % 3;

        #pragma unroll
        for (int k8 = 0; k8 < 4; k8++) {
            const int k0 = k8 * 8;
            const int m = warp * 16 + g;
            uint32_t ah[4], al[4];
            split_tf32(sA[s][m    ][k0 + t4    ], ah[0], al[0]);
            split_tf32(sA[s][m + 8][k0 + t4    ], ah[1], al[1]);
            split_tf32(sA[s][m    ][k0 + t4 + 4], ah[2], al[2]);
            split_tf32(sA[s][m + 8][k0 + t4 + 4], ah[3], al[3]);
            #pragma unroll
            for (int nf = 0; nf < 4; nf++) {  // nf == gate index
                int n = nf * 8 + g;
                uint32_t bh0, bl0, bh1, bl1;
                split_tf32(sB[s][k0 + t4    ][n], bh0, bl0);
                split_tf32(sB[s][k0 + t4 + 4][n], bh1, bl1);
                mma8(acc[nf], ah[0], ah[1], ah[2], ah[3], bh0, bh1);
                mma8(acc[nf], al[0], al[1], al[2], al[3], bh0, bh1);
                mma8(acc[nf], ah[0], ah[1], ah[2], ah[3], bl0, bl1);
            }
        }
    }

    // epilogue: add Zx, gates, cell update (thread-local across gates)
    #pragma unroll
    for (int e = 0; e < 4; e++) {             // c-reg e: row += (e>>1)*8, col = 2*t4 + (e&1)
        int r   = warp * 16 + g + (e >> 1) * 8;
        int jj  = 2 * t4 + (e & 1);
        int col = n0 + jj;
        float zi = acc[0][e] + Zx[(size_t)r * NGATE + col];
        float zj = acc[1][e] + Zx[(size_t)r * NGATE + 1024 + col];
        float zf = acc[2][e] + Zx[(size_t)r * NGATE + 2048 + col];
        float zo = acc[3][e] + Zx[(size_t)r * NGATE + 3072 + col];

        float cold = cbuf[r * KDIM + col];
        float ig = 1.f / (1.f + expf(-zi));
        float fg = 1.f / (1.f + expf(-(zf + 1.f)));   // FORGET_BIAS = 1.0
        float og = 1.f / (1.f + expf(-zo));
        float cn = cold * fg + ig * tanhf(zj);
        cbuf[r * KDIM + col] = cn;
        hout[(size_t)r * KDIM + col] = tanhf(cn) * og;
    }
}

// ---------------- per-call state zeroing (determinism) ----------------
__global__ void zero_state() {
    int i = blockIdx.x * blockDim.x + threadIdx.x;
    if (i < BATCH * KDIM) { g_c0[i] = 0.f; g_c1[i] = 0.f; }
}

// ======================================================================
extern "C" void kernel_launch(void* const* d_in, const int* in_sizes, int n_in,
                              void* d_out, int out_size)
{
    const float* X  = (const float*)d_in[0];   // [256, 64, 1024]
    const float* W0 = (const float*)d_in[1];   // [2048, 4096]
    const float* b0 = (const float*)d_in[2];   // [4096]
    const float* W1 = (const float*)d_in[3];   // [2048, 4096]
    const float* b1 = (const float*)d_in[4];   // [4096]
    float* out = (float*)d_out;                // [256, 64, 1024]

    float *Z0, *Z1, *H1, *c0, *c1, *zero;
    cudaGetSymbolAddress((void**)&Z0,   g_Z0);
    cudaGetSymbolAddress((void**)&Z1,   g_Z1);
    cudaGetSymbolAddress((void**)&H1,   g_H1);
    cudaGetSymbolAddress((void**)&c0,   g_c0);
    cudaGetSymbolAddress((void**)&c1,   g_c1);
    cudaGetSymbolAddress((void**)&zero, g_zero);

    const size_t ZSTEP = (size_t)BATCH * NGATE;   // 64*4096
    const size_t HSTEP = (size_t)BATCH * KDIM;    // 64*1024

    zero_state<<<64, 1024>>>();

    // Layer 0: Z0 = X @ W0[0:1024,:] + b0
    gemm_pre<<<dim3(NGATE / PBN, (T_STEPS * BATCH) / PBM), 256>>>(X, W0, b0, Z0);
    const float* W0h = W0 + (size_t)KDIM * NGATE;
    for (int t = 0; t < T_STEPS; t++) {
        const float* hp = (t == 0) ? zero : (H1 + (size_t)(t - 1) * HSTEP);
        lstm_step<<<128, 128>>>(Z0 + (size_t)t * ZSTEP, hp, c0, W0h, H1 + (size_t)t * HSTEP);
    }

    // Layer 1: Z1 = H1 @ W1[0:1024,:] + b1
    gemm_pre<<<dim3(NGATE / PBN, (T_STEPS * BATCH) / PBM), 256>>>(H1, W1, b1, Z1);
    const float* W1h = W1 + (size_t)KDIM * NGATE;
    for (int t = 0; t < T_STEPS; t++) {
        const float* hp = (t == 0) ? zero : (out + (size_t)(t - 1) * HSTEP);
        lstm_step<<<128, 128>>>(Z1 + (size_t)t * ZSTEP, hp, c1, W1h, out + (size_t)t * HSTEP);
    }
}

// round 5
// speedup vs baseline: 2.9921x; 2.9921x over previous
#include <cuda_runtime.h>
#include <cuda_bf16.h>
#include <cstdint>
#include <cmath>

// ---------------- problem sizes ----------------
#define T_STEPS 256
#define BATCH   64
#define KDIM    1024
#define NGATE   4096

typedef __nv_bfloat16 bf16;

// ---------------- scratch globals ----------------
__device__ float g_Z0[(size_t)T_STEPS * BATCH * NGATE];     // 256 MB
__device__ float g_Z1[(size_t)T_STEPS * BATCH * NGATE];     // 256 MB
__device__ float g_H1f[(size_t)T_STEPS * BATCH * KDIM];     // 64 MB (layer-0 fp32 dump)
__device__ bf16  g_Xhi[(size_t)T_STEPS * BATCH * KDIM];     // X split planes
__device__ bf16  g_Xlo[(size_t)T_STEPS * BATCH * KDIM];
__device__ bf16  g_H1hi[(size_t)T_STEPS * BATCH * KDIM];    // layer-0 h planes (= layer-1 A)
__device__ bf16  g_H1lo[(size_t)T_STEPS * BATCH * KDIM];
__device__ bf16  g_H2hi[(size_t)T_STEPS * BATCH * KDIM];    // layer-1 h planes (recurrence)
__device__ bf16  g_H2lo[(size_t)T_STEPS * BATCH * KDIM];
__device__ bf16  g_hz[2][BATCH * KDIM];                     // never written: h_{-1} = 0
__device__ float g_c0[BATCH * KDIM];
__device__ float g_c1[BATCH * KDIM];
// packed recurrent weights (fragment order), per layer, hi/lo planes
__device__ bf16  g_Ws0[2][(size_t)KDIM * NGATE];
__device__ bf16  g_Ws1[2][(size_t)KDIM * NGATE];
// packed pre-GEMM weights (fragment order), per layer, hi/lo planes
__device__ bf16  g_Wg0[2][(size_t)KDIM * NGATE];
__device__ bf16  g_Wg1[2][(size_t)KDIM * NGATE];

#define DEVFN __device__ __forceinline__

// ---------------- mma / cp.async helpers ----------------
DEVFN void mma16(float* c, const uint32_t* a, uint2 b) {
    asm volatile(
        "mma.sync.aligned.m16n8k16.row.col.f32.bf16.bf16.f32 "
        "{%0,%1,%2,%3},{%4,%5,%6,%7},{%8,%9},{%0,%1,%2,%3};"
        : "+f"(c[0]), "+f"(c[1]), "+f"(c[2]), "+f"(c[3])
        : "r"(a[0]), "r"(a[1]), "r"(a[2]), "r"(a[3]), "r"(b.x), "r"(b.y));
}
DEVFN void cp16(void* s, const void* g) {
    uint32_t sa = (uint32_t)__cvta_generic_to_shared(s);
    asm volatile("cp.async.cg.shared.global [%0], [%1], 16;" :: "r"(sa), "l"(g));
}
DEVFN void cp_commit() { asm volatile("cp.async.commit_group;"); }
template <int N> DEVFN void cp_wait() { asm volatile("cp.async.wait_group %0;" :: "n"(N)); }

DEVFN void split_bf16(float w, bf16& hi, bf16& lo) {
    hi = __float2bfloat16(w);
    lo = __float2bfloat16(w - __bfloat162float(hi));
}

// ======================================================================
// Pack kernels (run once per call; cheap elementwise)
// ======================================================================
// Step-kernel pack: dst[(cta*256 + kb*4+gt)*128 + lane*4 + reg*2 + hh]
__global__ void pack_stepW(const float* __restrict__ Wh, bf16* __restrict__ hi,
                           bf16* __restrict__ lo)
{
    size_t idx = (size_t)blockIdx.x * blockDim.x + threadIdx.x;
    if (idx >= (size_t)KDIM * NGATE) return;
    int k   = (int)(idx >> 12);          // / 4096
    int col = (int)(idx & 4095);
    int gt  = col >> 10, c = col & 1023;
    int cta = c >> 3,   cc = c & 7;
    int kb  = k >> 4,   kl = k & 15;
    int reg = kl >> 3, tg = (kl >> 1) & 3, hh = kl & 1;
    int lane = cc * 4 + tg;
    size_t dst = ((size_t)cta * 256 + kb * 4 + gt) * 128 + lane * 4 + reg * 2 + hh;
    bf16 h, l; split_bf16(Wh[idx], h, l);
    hi[dst] = h; lo[dst] = l;
}

// Pre-GEMM pack: dst[(n8*64 + kb)*128 + lane*4 + reg*2 + hh]
__global__ void pack_gemmW(const float* __restrict__ W, bf16* __restrict__ hi,
                           bf16* __restrict__ lo)
{
    size_t idx = (size_t)blockIdx.x * blockDim.x + threadIdx.x;
    if (idx >= (size_t)KDIM * NGATE) return;
    int k   = (int)(idx >> 12);
    int col = (int)(idx & 4095);
    int n8  = col >> 3, cc = col & 7;
    int kb  = k >> 4,   kl = k & 15;
    int reg = kl >> 3, tg = (kl >> 1) & 3, hh = kl & 1;
    int lane = cc * 4 + tg;
    size_t dst = ((size_t)n8 * 64 + kb) * 128 + lane * 4 + reg * 2 + hh;
    bf16 h, l; split_bf16(W[idx], h, l);
    hi[dst] = h; lo[dst] = l;
}

__global__ void split_planes(const float* __restrict__ A, bf16* __restrict__ hi,
                             bf16* __restrict__ lo, size_t n)
{
    size_t idx = (size_t)blockIdx.x * blockDim.x + threadIdx.x;
    if (idx >= n) return;
    bf16 h, l; split_bf16(A[idx], h, l);
    hi[idx] = h; lo[idx] = l;
}

// ======================================================================
// bf16 3-term pre-GEMM: C[M,4096] = A[M,1024]@W + bias
// Tile 128x128x32, 256 thr (8 warps: 4M x 2N), 2-stage cp.async.
// A: hi/lo row-major planes; B: pre-packed fragments.
// ======================================================================
#define GA_STRIDE 40
// SMEM: sA [2 stages][2 planes][128][40] bf16 = 40960 B
//       sB [2 stages][2 planes][16 n8][256] bf16 = 32768 B
#define G_SA_BYTES 40960
#define G_SMEM (G_SA_BYTES + 32768)

__global__ __launch_bounds__(256) void gemm_bf16(
    const bf16* __restrict__ Ahi, const bf16* __restrict__ Alo,
    const bf16* __restrict__ Bhi, const bf16* __restrict__ Blo,
    const float* __restrict__ bias, float* __restrict__ C)
{
    extern __shared__ char smem[];
    bf16* sA = (bf16*)smem;
    bf16* sB = (bf16*)(smem + G_SA_BYTES);

    const int tid  = threadIdx.x;
    const int warp = tid >> 5, lane = tid & 31;
    const int g  = lane >> 2, t4 = lane & 3;
    const int wm = warp >> 1, wn = warp & 1;
    const int m0 = blockIdx.y * 128;
    const int n0 = blockIdx.x * 128;
    const int n8base = n0 >> 3;

    float acc[2][8][4];
    #pragma unroll
    for (int i = 0; i < 2; i++)
        #pragma unroll
        for (int j = 0; j < 8; j++)
            #pragma unroll
            for (int k = 0; k < 4; k++) acc[i][j][k] = 0.f;

    auto issue = [&](int ks, int s) {
        #pragma unroll
        for (int p = 0; p < 4; p++) {            // A: 1024 cp16 (both planes)
            int id = p * 256 + tid;
            int plane = id >> 9, rem = id & 511;
            int row = rem >> 2, c8 = rem & 3;
            const bf16* src = (plane ? Alo : Ahi)
                + (size_t)(m0 + row) * KDIM + ks * 32 + c8 * 8;
            cp16(&sA[((size_t)(s * 2 + plane) * 128 + row) * GA_STRIDE + c8 * 8], src);
        }
        #pragma unroll
        for (int p = 0; p < 4; p++) {            // B: 1024 cp16
            int id = p * 256 + tid;
            int plane = id >> 9, rem = id & 511;
            int n8l = rem >> 5, r32 = rem & 31;
            const bf16* src = (plane ? Blo : Bhi)
                + ((size_t)(n8base + n8l) * 64 + ks * 2) * 128 + r32 * 8;
            cp16(&sB[((size_t)(s * 2 + plane) * 16 + n8l) * 256 + r32 * 8], src);
        }
    };

    issue(0, 0); cp_commit();

    for (int ks = 0; ks < KDIM / 32; ks++) {
        cp_wait<0>();
        __syncthreads();
        if (ks + 1 < KDIM / 32) issue(ks + 1, (ks + 1) & 1);
        cp_commit();
        const int s = ks & 1;

        #pragma unroll
        for (int kk = 0; kk < 2; kk++) {
            const int kloc = kk * 16 + t4 * 2;
            uint32_t ah[2][4], al[2][4];
            #pragma unroll
            for (int mf = 0; mf < 2; mf++) {
                int m = wm * 32 + mf * 16 + g;
                const bf16* p0 = &sA[((size_t)(s * 2) * 128 + m) * GA_STRIDE];
                const bf16* p1 = &sA[((size_t)(s * 2 + 1) * 128 + m) * GA_STRIDE];
                ah[mf][0] = *(const uint32_t*)(p0 + kloc);
                ah[mf][1] = *(const uint32_t*)(p0 + 8 * GA_STRIDE + kloc);
                ah[mf][2] = *(const uint32_t*)(p0 + kloc + 8);
                ah[mf][3] = *(const uint32_t*)(p0 + 8 * GA_STRIDE + kloc + 8);
                al[mf][0] = *(const uint32_t*)(p1 + kloc);
                al[mf][1] = *(const uint32_t*)(p1 + 8 * GA_STRIDE + kloc);
                al[mf][2] = *(const uint32_t*)(p1 + kloc + 8);
                al[mf][3] = *(const uint32_t*)(p1 + 8 * GA_STRIDE + kloc + 8);
            }
            #pragma unroll
            for (int nf = 0; nf < 8; nf++) {
                size_t base = ((size_t)(s * 2) * 16 + wn * 8 + nf) * 256 + kk * 128 + lane * 4;
                uint2 bhi = *(const uint2*)&sB[base];
                uint2 blo = *(const uint2*)&sB[base + 16 * 256];
                #pragma unroll
                for (int mf = 0; mf < 2; mf++) {
                    mma16(acc[mf][nf], ah[mf], bhi);
                    mma16(acc[mf][nf], al[mf], bhi);
                    mma16(acc[mf][nf], ah[mf], blo);
                }
            }
        }
    }

    #pragma unroll
    for (int mf = 0; mf < 2; mf++) {
        #pragma unroll
        for (int nf = 0; nf < 8; nf++) {
            int col = n0 + (wn * 8 + nf) * 8 + 2 * t4;
            int r0  = m0 + wm * 32 + mf * 16 + g;
            float bv0 = bias[col], bv1 = bias[col + 1];
            C[(size_t)r0 * NGATE + col]           = acc[mf][nf][0] + bv0;
            C[(size_t)r0 * NGATE + col + 1]       = acc[mf][nf][1] + bv1;
            C[(size_t)(r0 + 8) * NGATE + col]     = acc[mf][nf][2] + bv0;
            C[(size_t)(r0 + 8) * NGATE + col + 1] = acc[mf][nf][3] + bv1;
        }
    }
}

// ======================================================================
// LSTM step (one launch per step; no barriers).
// 128 CTAs x 128 thr. CTA owns 8 h-cols -> 32 z-cols (4 gates x 8).
// Packed-W cp.async (zero split ALU); pre-split h planes; c in global.
// 3-stage K pipeline, KT=64 (16 tiles).
// ======================================================================
#define SH_STRIDE 72
// SMEM: W [3 stages][2 planes][2048] bf16 = 24576 B
//       h [3 stages][2 planes][64][72] bf16 = 55296 B
#define S_W_BYTES 24576
#define S_SMEM (S_W_BYTES + 3 * 2 * 64 * SH_STRIDE * 2)

__global__ __launch_bounds__(128, 1) void lstm_step2(
    const float* __restrict__ Zx,        // [64][4096] this step (bias added)
    const bf16* __restrict__ hhi,        // [64][1024] prev-h hi plane
    const bf16* __restrict__ hlo,        //            prev-h lo plane
    float* __restrict__ cbuf,            // [64][1024]
    const bf16* __restrict__ Wphi,       // packed Wh hi plane
    const bf16* __restrict__ Wplo,       //            lo plane
    float* __restrict__ hout,            // [64][1024] fp32 out this step
    bf16* __restrict__ hhi_out,          // [64][1024] h hi plane this step
    bf16* __restrict__ hlo_out,
    int first)
{
    extern __shared__ char smem[];
    bf16* sW = (bf16*)smem;
    bf16* sH = (bf16*)(smem + S_W_BYTES);

    const int tid  = threadIdx.x;
    const int warp = tid >> 5, lane = tid & 31;
    const int g    = lane >> 2, t4 = lane & 3;
    const int n0   = blockIdx.x * 8;
    const int mrow = warp * 16 + g;
    const size_t ctaW = (size_t)blockIdx.x * 32768;

    // prefetch Zx and c early (hidden under MMA loop)
    float zr[4][4];
    #pragma unroll
    for (int gt = 0; gt < 4; gt++)
        #pragma unroll
        for (int rr = 0; rr < 2; rr++) {
            float2 v = __ldg((const float2*)(Zx + (size_t)(mrow + rr * 8) * NGATE
                                             + gt * 1024 + n0 + t4 * 2));
            zr[gt][rr * 2] = v.x; zr[gt][rr * 2 + 1] = v.y;
        }
    float cold[4] = {0.f, 0.f, 0.f, 0.f};
    if (!first) {
        #pragma unroll
        for (int rr = 0; rr < 2; rr++) {
            float2 cv = __ldg((const float2*)(cbuf + (size_t)(mrow + rr * 8) * KDIM
                                              + n0 + t4 * 2));
            cold[rr * 2] = cv.x; cold[rr * 2 + 1] = cv.y;
        }
    }

    float acc[4][4] = {};

    if (!first) {
        auto issue = [&](int tile, int st) {
            #pragma unroll
            for (int q = 0; q < 8; q++) {        // h: 1024 cp16
                int id = q * 128 + tid;
                int plane = id >> 9, rem = id & 511;
                int row = rem >> 3, c8 = rem & 7;
                const bf16* src = (plane ? hlo : hhi)
                    + (size_t)row * KDIM + tile * 64 + c8 * 8;
                cp16(&sH[((size_t)(st * 2 + plane) * 64 + row) * SH_STRIDE + c8 * 8], src);
            }
            #pragma unroll
            for (int q = 0; q < 4; q++) {        // W: 512 cp16
                int id = q * 128 + tid;
                int plane = id >> 8, rem = id & 255;
                const bf16* src = (plane ? Wplo : Wphi) + ctaW + (size_t)tile * 2048 + rem * 8;
                cp16(&sW[(size_t)(st * 2 + plane) * 2048 + rem * 8], src);
            }
        };

        issue(0, 0); cp_commit();
        issue(1, 1); cp_commit();

        for (int tile = 0; tile < 16; tile++) {
            cp_wait<1>();
            __syncthreads();
            if (tile + 2 < 16) issue(tile + 2, (tile + 2) % 3);
            cp_commit();
            const int st = tile % 3;
            const bf16* h0 = &sH[(size_t)(st * 2) * 64 * SH_STRIDE];
            const bf16* h1 = &sH[(size_t)(st * 2 + 1) * 64 * SH_STRIDE];
            const bf16* w0 = &sW[(size_t)(st * 2) * 2048];

            #pragma unroll
            for (int kbl = 0; kbl < 4; kbl++) {
                const int kloc = kbl * 16 + t4 * 2;
                uint32_t ahi[4], alo[4];
                ahi[0] = *(const uint32_t*)(h0 + (size_t)mrow * SH_STRIDE + kloc);
                ahi[1] = *(const uint32_t*)(h0 + (size_t)(mrow + 8) * SH_STRIDE + kloc);
                ahi[2] = *(const uint32_t*)(h0 + (size_t)mrow * SH_STRIDE + kloc + 8);
                ahi[3] = *(const uint32_t*)(h0 + (size_t)(mrow + 8) * SH_STRIDE + kloc + 8);
                alo[0] = *(const uint32_t*)(h1 + (size_t)mrow * SH_STRIDE + kloc);
                alo[1] = *(const uint32_t*)(h1 + (size_t)(mrow + 8) * SH_STRIDE + kloc);
                alo[2] = *(const uint32_t*)(h1 + (size_t)mrow * SH_STRIDE + kloc + 8);
                alo[3] = *(const uint32_t*)(h1 + (size_t)(mrow + 8) * SH_STRIDE + kloc + 8);
                #pragma unroll
                for (int gt = 0; gt < 4; gt++) {
                    const bf16* wb = w0 + (size_t)(kbl * 4 + gt) * 128 + lane * 4;
                    uint2 bhi = *(const uint2*)wb;
                    uint2 blo = *(const uint2*)(wb + 2048);
                    mma16(acc[gt], ahi, bhi);
                    mma16(acc[gt], alo, bhi);
                    mma16(acc[gt], ahi, blo);
                }
            }
        }
    }

    // epilogue
    float hv[4], cn_[4];
    #pragma unroll
    for (int e = 0; e < 4; e++) {
        float zi = acc[0][e] + zr[0][e];
        float zj = acc[1][e] + zr[1][e];
        float zf = acc[2][e] + zr[2][e];
        float zo = acc[3][e] + zr[3][e];
        float ig = 1.f / (1.f + expf(-zi));
        float fg = 1.f / (1.f + expf(-(zf + 1.f)));   // FORGET_BIAS = 1.0
        float og = 1.f / (1.f + expf(-zo));
        float cn = cold[e] * fg + ig * tanhf(zj);
        cn_[e] = cn;
        hv[e] = tanhf(cn) * og;
    }
    #pragma unroll
    for (int rr = 0; rr < 2; rr++) {
        int r   = mrow + rr * 8;
        int col = n0 + t4 * 2;
        float h0v = hv[rr * 2], h1v = hv[rr * 2 + 1];
        bf16 h0h, h0l, h1h, h1l;
        split_bf16(h0v, h0h, h0l);
        split_bf16(h1v, h1h, h1l);
        *(float2*)&cbuf[(size_t)r * KDIM + col] = make_float2(cn_[rr * 2], cn_[rr * 2 + 1]);
        *(float2*)&hout[(size_t)r * KDIM + col] = make_float2(h0v, h1v);
        *(__nv_bfloat162*)&hhi_out[(size_t)r * KDIM + col] = __halves2bfloat162(h0h, h1h);
        *(__nv_bfloat162*)&hlo_out[(size_t)r * KDIM + col] = __halves2bfloat162(h0l, h1l);
    }
}

// ======================================================================
extern "C" void kernel_launch(void* const* d_in, const int* in_sizes, int n_in,
                              void* d_out, int out_size)
{
    const float* X  = (const float*)d_in[0];
    const float* W0 = (const float*)d_in[1];
    const float* b0 = (const float*)d_in[2];
    const float* W1 = (const float*)d_in[3];
    const float* b1 = (const float*)d_in[4];
    float* out = (float*)d_out;

    float *Z0, *Z1, *H1f, *c0, *c1;
    bf16 *Xhi, *Xlo, *H1hi, *H1lo, *H2hi, *H2lo, *hz, *Ws0, *Ws1, *Wg0, *Wg1;
    cudaGetSymbolAddress((void**)&Z0,   g_Z0);
    cudaGetSymbolAddress((void**)&Z1,   g_Z1);
    cudaGetSymbolAddress((void**)&H1f,  g_H1f);
    cudaGetSymbolAddress((void**)&c0,   g_c0);
    cudaGetSymbolAddress((void**)&c1,   g_c1);
    cudaGetSymbolAddress((void**)&Xhi,  g_Xhi);
    cudaGetSymbolAddress((void**)&Xlo,  g_Xlo);
    cudaGetSymbolAddress((void**)&H1hi, g_H1hi);
    cudaGetSymbolAddress((void**)&H1lo, g_H1lo);
    cudaGetSymbolAddress((void**)&H2hi, g_H2hi);
    cudaGetSymbolAddress((void**)&H2lo, g_H2lo);
    cudaGetSymbolAddress((void**)&hz,   g_hz);
    cudaGetSymbolAddress((void**)&Ws0,  g_Ws0);
    cudaGetSymbolAddress((void**)&Ws1,  g_Ws1);
    cudaGetSymbolAddress((void**)&Wg0,  g_Wg0);
    cudaGetSymbolAddress((void**)&Wg1,  g_Wg1);

    const size_t WPLANE = (size_t)KDIM * NGATE;    // 4 M elems per plane
    const size_t ZSTEP  = (size_t)BATCH * NGATE;   // 262144
    const size_t HSTEP  = (size_t)BATCH * KDIM;    // 65536
    const size_t NX     = (size_t)T_STEPS * HSTEP; // 16 M

    cudaFuncSetAttribute(gemm_bf16,  cudaFuncAttributeMaxDynamicSharedMemorySize, G_SMEM);
    cudaFuncSetAttribute(lstm_step2, cudaFuncAttributeMaxDynamicSharedMemorySize, S_SMEM);

    // ---- packs & splits ----
    int pb = 256;
    int pgW = (int)((WPLANE + pb - 1) / pb);
    pack_gemmW<<<pgW, pb>>>(W0, Wg0, Wg0 + WPLANE);
    pack_gemmW<<<pgW, pb>>>(W1, Wg1, Wg1 + WPLANE);
    pack_stepW<<<pgW, pb>>>(W0 + WPLANE, Ws0, Ws0 + WPLANE);
    pack_stepW<<<pgW, pb>>>(W1 + WPLANE, Ws1, Ws1 + WPLANE);
    split_planes<<<(int)((NX + 255) / 256), 256>>>(X, Xhi, Xlo, NX);

    // ---- layer 0 ----
    gemm_bf16<<<dim3(NGATE / 128, (T_STEPS * BATCH) / 128), 256, G_SMEM>>>(
        Xhi, Xlo, Wg0, Wg0 + WPLANE, b0, Z0);
    for (int t = 0; t < T_STEPS; t++) {
        const bf16* ph = (t == 0) ? hz : (H1hi + (size_t)(t - 1) * HSTEP);
        const bf16* pl = (t == 0) ? (hz + HSTEP) : (H1lo + (size_t)(t - 1) * HSTEP);
        lstm_step2<<<128, 128, S_SMEM>>>(
            Z0 + (size_t)t * ZSTEP, ph, pl, c0, Ws0, Ws0 + WPLANE,
            H1f + (size_t)t * HSTEP, H1hi + (size_t)t * HSTEP, H1lo + (size_t)t * HSTEP,
            t == 0 ? 1 : 0);
    }

    // ---- layer 1 ----
    gemm_bf16<<<dim3(NGATE / 128, (T_STEPS * BATCH) / 128), 256, G_SMEM>>>(
        H1hi, H1lo, Wg1, Wg1 + WPLANE, b1, Z1);
    for (int t = 0; t < T_STEPS; t++) {
        const bf16* ph = (t == 0) ? hz : (H2hi + (size_t)(t - 1) * HSTEP);
        const bf16* pl = (t == 0) ? (hz + HSTEP) : (H2lo + (size_t)(t - 1) * HSTEP);
        lstm_step2<<<128, 128, S_SMEM>>>(
            Z1 + (size_t)t * ZSTEP, ph, pl, c1, Ws1, Ws1 + WPLANE,
            out + (size_t)t * HSTEP, H2hi + (size_t)t * HSTEP, H2lo + (size_t)t * HSTEP,
            t == 0 ? 1 : 0);
    }
}